// round 11
// baseline (speedup 1.0000x reference)
#include <cuda_runtime.h>
#include <cuda_bf16.h>

// Problem dims (fixed by setup_inputs)
#define T_DIM 2048
#define N_DIM 128
#define C_DIM 96
#define NC    (N_DIM * C_DIM)
#define L_DIM 200
#define S_EXT 401            // 2*L+1
#define NWARP 2
#define NTHR  (NWARP * 32)   // 64
#define KWIN  8              // ticks per window (= barrier period)
#define SPT   8              // states per thread
#define OWNS  240            // owned slots per warp (30 threads * 8)
#define HALO  16             // left halo slots per warp (= 2*KWIN = 2 threads)
#define NREC  ((NWARP * OWNS + HALO) / SPT)   // 62 records
#define NSTG  12             // staged floats per thread per window (768/64)
#define LN2   0.69314718055994530942f
#define FIXSCALE 1024.0      // fixed-point scale for deterministic reduction

// Deterministic cross-CTA reduction state (reset by the last CTA each call).
__device__ unsigned long long g_acc  = 0ull;
__device__ unsigned int       g_done = 0u;

// One CTA per batch element. CTC forward, per-thread block-floating-point:
// 8 adjacent states per thread (4 blank + 4 label) as linear floats v0..v7
// plus a power-of-two scale iM. The cross-lane shfl_up(v7) result re-enters
// the carried chain only after 4 ticks (dependence moves 2 slots/tick), so
// the per-tick critical path is the in-thread FMA chain (~12cy). P values
// are register-gathered per window; SMEM commit runs at window top; one
// barrier per 8 ticks; depth-3 LDG staging pipeline.
__global__ __launch_bounds__(NTHR, 1)
void ctc_forward_kernel(const float* __restrict__ predicts,   // (T, N, C)
                        const int*   __restrict__ labels,     // (N, L)
                        const int*   __restrict__ preds_lengths,
                        const int*   __restrict__ label_lengths,
                        float*       __restrict__ out)
{
    const int tid  = threadIdx.x;
    const int n    = blockIdx.x;
    const int w    = tid >> 5;
    const int lane = tid & 31;
    const int sb   = OWNS * w - HALO + SPT * lane;   // first (even) slot
    const bool own = (lane >= HALO / SPT);           // lanes 0..1 are halo
    const int pidx = (sb + HALO) >> 3;               // 30*w + lane

    __shared__ float4 As0[2][NREC];   // ping-pong (v0..v3)
    __shared__ float4 As1[2][NREC];   // ping-pong (v4..v7)
    __shared__ int    Ai[2][NREC];    // ping-pong iM
    __shared__ float  Pb[2 * KWIN * C_DIM];  // linear probs, double-buffered
    __shared__ float  FinV[2];
    __shared__ int    FinI[2];

    if (tid < HALO / SPT) {           // permanent zero-pads for slots < 0
        As0[0][tid] = make_float4(0.f, 0.f, 0.f, 0.f);
        As0[1][tid] = make_float4(0.f, 0.f, 0.f, 0.f);
        As1[0][tid] = make_float4(0.f, 0.f, 0.f, 0.f);
        As1[1][tid] = make_float4(0.f, 0.f, 0.f, 0.f);
        Ai[0][tid] = 0; Ai[1][tid] = 0;
    }

    // Odd slots sb+1,3,5,7 carry labels; even slots are blanks (no skip).
    int   ext[4];
    float sk[4];
#pragma unroll
    for (int i = 0; i < 4; ++i) {
        const int so = sb + 2 * i + 1;
        ext[i] = 0; sk[i] = 0.0f;
        if (so >= 1 && so < S_EXT) {
            const int k = so >> 1;
            ext[i] = labels[n * L_DIM + k];
            if (so >= 3) sk[i] = (ext[i] != labels[n * L_DIM + k - 1]) ? 1.0f : 0.0f;
        }
    }
    const int len     = preds_lengths[n];
    const int end     = 2 * label_lengths[n];
    const int lastwin = (len - 1) >> 3;

    // Cooperative staging geometry: 8 rows x 96 classes = 768 floats, 12/thread.
    const float* gbase = predicts + (size_t)n * C_DIM;
    int off_q[NSTG]; int r_q[NSTG];
#pragma unroll
    for (int q = 0; q < NSTG; ++q) {
        const int idx = tid + q * NTHR;
        const int r = idx / C_DIM, c = idx - r * C_DIM;
        r_q[q]   = r;
        off_q[q] = r * NC + c;
    }

    // Pre-stage rows [0,8) into buffer 0; prime the depth-3 register pipeline
    // with LDGs for windows 1..3 (rows 8..31; len >= 1024 so always valid).
    float stgA[NSTG], stgB[NSTG], stgC[NSTG];
#pragma unroll
    for (int q = 0; q < NSTG; ++q) {
        Pb[tid + q * NTHR] = __expf(__ldg(gbase + off_q[q]));
        stgA[q] = __ldg(gbase + off_q[q] + (size_t)(1 * KWIN) * NC);
        stgB[q] = __ldg(gbase + off_q[q] + (size_t)(2 * KWIN) * NC);
        stgC[q] = __ldg(gbase + off_q[q] + (size_t)(3 * KWIN) * NC);
    }
    __syncthreads();

    float v0 = (sb == 0) ? 1.0f : 0.0f;   // virtual alpha_{-1}: 1 at slot 0
    float v1 = 0.f, v2 = 0.f, v3 = 0.f, v4 = 0.f, v5 = 0.f, v6 = 0.f, v7 = 0.f;
    int   iM = 0;
    float fp = (lane == 0) ? 0.0f : 1.0f; // all scales equal at t=0
    const int nwin = (len + KWIN - 1) >> 3;   // len uniform per CTA

    for (int win = 0; win < nwin; ++win) {
        // --- window top: gather this window's P values into registers ---
        const float* prow = Pb + ((win & 1) ? KWIN * C_DIM : 0);
        float gb[KWIN], ge0[KWIN], ge1[KWIN], ge2[KWIN], ge3[KWIN];
#pragma unroll
        for (int j = 0; j < KWIN; ++j) {
            const float* r = prow + j * C_DIM;
            gb[j]  = r[0];          // blank (broadcast, conflict-free)
            ge0[j] = r[ext[0]];
            ge1[j] = r[ext[1]];
            ge2[j] = r[ext[2]];
            ge3[j] = r[ext[3]];
        }

        // --- commit next window's rows into the OTHER buffer, then refill
        //     the staging set with rows 4 windows ahead ---
        {
            float* dst = Pb + ((win & 1) ? 0 : KWIN * C_DIM);
            const int tnext = (win + 4) * KWIN;
            const int set   = win % 3;
            if (set == 0) {
#pragma unroll
                for (int q = 0; q < NSTG; ++q) {
                    dst[tid + q * NTHR] = __expf(stgA[q]);
                    stgA[q] = (tnext + r_q[q] < T_DIM)
                              ? __ldg(gbase + off_q[q] + (size_t)tnext * NC) : 0.0f;
                }
            } else if (set == 1) {
#pragma unroll
                for (int q = 0; q < NSTG; ++q) {
                    dst[tid + q * NTHR] = __expf(stgB[q]);
                    stgB[q] = (tnext + r_q[q] < T_DIM)
                              ? __ldg(gbase + off_q[q] + (size_t)tnext * NC) : 0.0f;
                }
            } else {
#pragma unroll
                for (int q = 0; q < NSTG; ++q) {
                    dst[tid + q * NTHR] = __expf(stgC[q]);
                    stgC[q] = (tnext + r_q[q] < T_DIM)
                              ? __ldg(gbase + off_q[q] + (size_t)tnext * NC) : 0.0f;
                }
            }
        }

        // --- tick loop: 1 shfl + in-thread FMA dataflow ---
        if (win != lastwin) {
#pragma unroll
            for (int j = 0; j < KWIN; ++j) {
                const float vp = __shfl_up_sync(0xffffffffu, v7, 1) * fp;
                const float P0 = gb[j];
                const float nv0 = (v0 + vp) * P0;
                const float nv1 = (v1 + v0 + vp * sk[0]) * ge0[j];
                const float nv2 = (v2 + v1) * P0;
                const float nv3 = (v3 + v2 + v1 * sk[1]) * ge1[j];
                const float nv4 = (v4 + v3) * P0;
                const float nv5 = (v5 + v4 + v3 * sk[2]) * ge2[j];
                const float nv6 = (v6 + v5) * P0;
                const float nv7 = (v7 + v6 + v5 * sk[3]) * ge3[j];
                v0 = nv0; v1 = nv1; v2 = nv2; v3 = nv3;
                v4 = nv4; v5 = nv5; v6 = nv6; v7 = nv7;
            }
        } else {
#pragma unroll
            for (int j = 0; j < KWIN; ++j) {
                const int t = (win << 3) + j;
                const float vp = __shfl_up_sync(0xffffffffu, v7, 1) * fp;
                const float P0 = gb[j];
                const float nv0 = (v0 + vp) * P0;
                const float nv1 = (v1 + v0 + vp * sk[0]) * ge0[j];
                const float nv2 = (v2 + v1) * P0;
                const float nv3 = (v3 + v2 + v1 * sk[1]) * ge1[j];
                const float nv4 = (v4 + v3) * P0;
                const float nv5 = (v5 + v4 + v3 * sk[2]) * ge2[j];
                const float nv6 = (v6 + v5) * P0;
                const float nv7 = (v7 + v6 + v5 * sk[3]) * ge3[j];
                v0 = nv0; v1 = nv1; v2 = nv2; v3 = nv3;
                v4 = nv4; v5 = nv5; v6 = nv6; v7 = nv7;

                if (t == len - 1 && own) {       // record final states
                    if (sb == end)         { FinV[0] = v0; FinI[0] = iM; }
                    if (sb + 2 == end)     { FinV[0] = v2; FinI[0] = iM; }
                    if (sb + 4 == end)     { FinV[0] = v4; FinI[0] = iM; }
                    if (sb + 6 == end)     { FinV[0] = v6; FinI[0] = iM; }
                    if (sb + 1 == end - 1) { FinV[1] = v1; FinI[1] = iM; }
                    if (sb + 3 == end - 1) { FinV[1] = v3; FinI[1] = iM; }
                    if (sb + 5 == end - 1) { FinV[1] = v5; FinI[1] = iM; }
                    if (sb + 7 == end - 1) { FinV[1] = v7; FinI[1] = iM; }
                }
            }
        }

        // ---- window boundary ----
        // 1) per-thread renorm: pull exponent of max(v0..v7) into iM.
        const float mx = fmaxf(fmaxf(fmaxf(v0, v1), fmaxf(v2, v3)),
                               fmaxf(fmaxf(v4, v5), fmaxf(v6, v7)));
        if (mx > 0.0f) {
            const int e = (int)(__float_as_uint(mx) >> 23) - 127;
            iM += e;
            const float sc = __int_as_float((unsigned)(127 - e) << 23);
            v0 *= sc; v1 *= sc; v2 *= sc; v3 *= sc;
            v4 *= sc; v5 *= sc; v6 *= sc; v7 *= sc;
        }
        // 2) owners publish; barrier; reload record + adoption scale in parallel.
        const int ab = win & 1;
        if (own) {
            As0[ab][pidx] = make_float4(v0, v1, v2, v3);
            As1[ab][pidx] = make_float4(v4, v5, v6, v7);
            Ai[ab][pidx]  = iM;
        }
        __syncthreads();
        const float4 pa = As0[ab][pidx];
        const float4 pb = As1[ab][pidx];
        const int    iMr = Ai[ab][pidx];
        const int    iMa = Ai[ab][(pidx >= 2) ? (pidx - 2) : 0];  // parallel load
        v0 = pa.x; v1 = pa.y; v2 = pa.z; v3 = pa.w;
        v4 = pb.x; v5 = pb.y; v6 = pb.z; v7 = pb.w;
        // 3) unreached threads adopt the propagated scale (select, no extra hop).
        const float mr = fmaxf(fmaxf(fmaxf(v0, v1), fmaxf(v2, v3)),
                               fmaxf(fmaxf(v4, v5), fmaxf(v6, v7)));
        iM = (mr == 0.0f) ? iMa : iMr;

        // 4) fixed per-window neighbor rescale from post-adoption scales.
        const int iMp = __shfl_up_sync(0xffffffffu, iM, 1);
        int k = iMp - iM;
        k = (k > 125) ? 125 : ((k < -127) ? -127 : k);
        fp = __int_as_float((unsigned)(k + 127) << 23);  // k=-127 -> exact 0
        if (lane == 0) fp = 0.0f;
    }

    __syncthreads();
    if (tid == 0) {
        const float f0 = __log2f(FinV[0]) + (float)FinI[0];
        const float f1 = __log2f(FinV[1]) + (float)FinI[1];
        const float mm   = fmaxf(f0, f1);
        const float fin2 = mm + __log2f(exp2f(f0 - mm) + exp2f(f1 - mm));
        const float ctc  = -(fin2 * LN2);
        const float fw   = 1.0f - __expf(-ctc);     // focal: alpha=1, gamma=2
        const double contrib = (double)(ctc * (fw * fw));

        // Deterministic reduction: integer fixed-point atomic (exactly
        // associative), last CTA converts + writes + resets for next replay.
        const unsigned long long q =
            (unsigned long long)(long long)(contrib * FIXSCALE + 0.5);
        atomicAdd(&g_acc, q);
        __threadfence();
        const unsigned rank = atomicAdd(&g_done, 1u);
        if (rank == N_DIM - 1) {
            const unsigned long long total = atomicAdd(&g_acc, 0ull);
            out[0] = (float)((double)total / FIXSCALE);
            g_acc  = 0ull;          // reset for the next graph replay
            g_done = 0u;
        }
    }
}

extern "C" void kernel_launch(void* const* d_in, const int* in_sizes, int n_in,
                              void* d_out, int out_size)
{
    const float* predicts      = (const float*)d_in[0];
    const int*   labels        = (const int*)  d_in[1];
    // d_in[2] = ref_labels (unused), d_in[5] = ref_length (unused)
    const int*   preds_lengths = (const int*)  d_in[3];
    const int*   label_lengths = (const int*)  d_in[4];
    float*       out           = (float*)d_out;

    ctc_forward_kernel<<<N_DIM, NTHR>>>(predicts, labels, preds_lengths,
                                        label_lengths, out);
}

// round 12
// speedup vs baseline: 1.0592x; 1.0592x over previous
#include <cuda_runtime.h>
#include <cuda_bf16.h>

// Problem dims (fixed by setup_inputs)
#define T_DIM 2048
#define N_DIM 128
#define C_DIM 96
#define NC    (N_DIM * C_DIM)
#define L_DIM 200
#define S_EXT 401            // 2*L+1
#define NWARP 5
#define NTHR  (NWARP * 32)   // 160
#define KWIN  16             // ticks per window (= barrier period)
#define RENP  8              // local renorm period (no barrier needed)
#define SPT   4              // states per thread
#define OWNS  96             // owned slots per warp (24 threads * 4)
#define HALO  32             // left halo slots per warp (= 2*KWIN = 8 threads)
#define NREC  ((NWARP * OWNS + HALO) / SPT)   // 128 records
#define NROWF (KWIN * C_DIM) // floats per window buffer (1536)
#define NSTG  10             // staged floats per thread (ceil(1536/160))
#define LN2   0.69314718055994530942f
#define FIXSCALE 1024.0      // fixed-point scale for deterministic reduction

// Deterministic cross-CTA reduction state (reset by the last CTA each call).
__device__ unsigned long long g_acc  = 0ull;
__device__ unsigned int       g_done = 0u;

// One CTA per batch element. CTC forward, per-thread block-floating-point
// (4 adjacent states/thread, linear floats + power-of-two scale iM).
// R12: KWIN=16 halo windows (halo 32 slots = 8 threads) halve the barrier
// count vs R10; numerical safety is preserved by a BARRIER-FREE local renorm
// + fp rebuild at mid-window (renorm needs no cross-warp data). P values are
// register-gathered per window; SMEM commit at window top; depth-3 LDG
// staging pipeline; in-kernel deterministic fixed-point reduction.
__global__ __launch_bounds__(NTHR, 1)
void ctc_forward_kernel(const float* __restrict__ predicts,   // (T, N, C)
                        const int*   __restrict__ labels,     // (N, L)
                        const int*   __restrict__ preds_lengths,
                        const int*   __restrict__ label_lengths,
                        float*       __restrict__ out)
{
    const int tid  = threadIdx.x;
    const int n    = blockIdx.x;
    const int w    = tid >> 5;
    const int lane = tid & 31;
    const int sb   = OWNS * w - HALO + SPT * lane;   // first (even) slot
    const bool own = (lane >= HALO / SPT);           // lanes 0..7 are halo
    const int pidx = (sb + HALO) >> 2;               // 24*w + lane

    __shared__ float4 As[2][NREC];    // ping-pong (v0,v1,v2,v3)
    __shared__ int    Ai[2][NREC];    // ping-pong iM
    __shared__ float  Pb[2 * NROWF];  // linear probs, double-buffered
    __shared__ float  FinV[2];
    __shared__ int    FinI[2];

    if (tid < HALO / SPT) {           // permanent zero-pads for slots < 0
        As[0][tid] = make_float4(0.f, 0.f, 0.f, 0.f);
        As[1][tid] = make_float4(0.f, 0.f, 0.f, 0.f);
        Ai[0][tid] = 0; Ai[1][tid] = 0;
    }

    // Odd slots sb+1, sb+3 carry labels; even slots are blanks (no skip).
    int ext1 = 0, ext3 = 0;
    float sk1 = 0.0f, sk3 = 0.0f;
    {
        const int s1 = sb + 1, s3 = sb + 3;
        if (s1 >= 1 && s1 < S_EXT) {
            const int k = s1 >> 1;
            ext1 = labels[n * L_DIM + k];
            if (s1 >= 3) sk1 = (ext1 != labels[n * L_DIM + k - 1]) ? 1.0f : 0.0f;
        }
        if (s3 >= 1 && s3 < S_EXT) {
            const int k = s3 >> 1;
            ext3 = labels[n * L_DIM + k];
            if (s3 >= 3) sk3 = (ext3 != labels[n * L_DIM + k - 1]) ? 1.0f : 0.0f;
        }
    }
    const int len     = preds_lengths[n];
    const int end     = 2 * label_lengths[n];
    const int lastwin = (len - 1) >> 4;

    // Cooperative staging geometry: 16 rows x 96 classes = 1536 floats, 10/thr.
    const float* gbase = predicts + (size_t)n * C_DIM;
    int  off_q[NSTG], r_q[NSTG];
    bool ok_q[NSTG];
#pragma unroll
    for (int q = 0; q < NSTG; ++q) {
        const int idx = tid + q * NTHR;
        ok_q[q] = (idx < NROWF);
        const int ii = ok_q[q] ? idx : 0;
        const int r = ii / C_DIM, c = ii - r * C_DIM;
        r_q[q]   = r;
        off_q[q] = r * NC + c;
    }

    // Pre-stage rows [0,16) into buffer 0; prime the depth-3 register pipeline
    // with LDGs for windows 1..3 (rows 16..63; len >= 1024 so always valid).
    float stgA[NSTG], stgB[NSTG], stgC[NSTG];
#pragma unroll
    for (int q = 0; q < NSTG; ++q) {
        if (ok_q[q]) Pb[tid + q * NTHR] = __expf(__ldg(gbase + off_q[q]));
        stgA[q] = __ldg(gbase + off_q[q] + (size_t)(1 * KWIN) * NC);
        stgB[q] = __ldg(gbase + off_q[q] + (size_t)(2 * KWIN) * NC);
        stgC[q] = __ldg(gbase + off_q[q] + (size_t)(3 * KWIN) * NC);
    }
    __syncthreads();

    float v0 = (sb == 0) ? 1.0f : 0.0f;   // virtual alpha_{-1}: 1 at slot 0
    float v1 = 0.f, v2 = 0.f, v3 = 0.f;
    int   iM = 0;
    float fp = (lane == 0) ? 0.0f : 1.0f; // all scales equal at t=0
    const int nwin = (len + KWIN - 1) >> 4;   // len uniform per CTA

    for (int win = 0; win < nwin; ++win) {
        // --- window top: gather this window's P values into registers ---
        const float* prow = Pb + ((win & 1) ? NROWF : 0);
        float g0[KWIN], g1[KWIN], g3[KWIN];
#pragma unroll
        for (int j = 0; j < KWIN; ++j) {
            const float* r = prow + j * C_DIM;
            g0[j] = r[0];          // blank (broadcast, conflict-free)
            g1[j] = r[ext1];
            g3[j] = r[ext3];
        }

        // --- commit next window's rows into the OTHER buffer, then refill
        //     the staging set with rows 4 windows ahead ---
        {
            float* dst = Pb + ((win & 1) ? 0 : NROWF);
            const int tnext = (win + 4) * KWIN;
            const int set   = win % 3;
            if (set == 0) {
#pragma unroll
                for (int q = 0; q < NSTG; ++q) {
                    if (ok_q[q]) dst[tid + q * NTHR] = __expf(stgA[q]);
                    stgA[q] = (tnext + r_q[q] < T_DIM)
                              ? __ldg(gbase + off_q[q] + (size_t)tnext * NC) : 0.0f;
                }
            } else if (set == 1) {
#pragma unroll
                for (int q = 0; q < NSTG; ++q) {
                    if (ok_q[q]) dst[tid + q * NTHR] = __expf(stgB[q]);
                    stgB[q] = (tnext + r_q[q] < T_DIM)
                              ? __ldg(gbase + off_q[q] + (size_t)tnext * NC) : 0.0f;
                }
            } else {
#pragma unroll
                for (int q = 0; q < NSTG; ++q) {
                    if (ok_q[q]) dst[tid + q * NTHR] = __expf(stgC[q]);
                    stgC[q] = (tnext + r_q[q] < T_DIM)
                              ? __ldg(gbase + off_q[q] + (size_t)tnext * NC) : 0.0f;
                }
            }
        }

        // --- tick loop: 1 shfl + 8 FMA per tick; barrier-free local renorm
        //     + fp rebuild at mid-window (tick RENP) ---
        const bool isLast = (win == lastwin);
#pragma unroll
        for (int j = 0; j < KWIN; ++j) {
            if (j == RENP) {
                // local renorm (no cross-warp data needed)
                const float mx = fmaxf(fmaxf(v0, v1), fmaxf(v2, v3));
                if (mx > 0.0f) {
                    const int e = (int)(__float_as_uint(mx) >> 23) - 127;
                    iM += e;
                    const float sc = __int_as_float((unsigned)(127 - e) << 23);
                    v0 *= sc; v1 *= sc; v2 *= sc; v3 *= sc;
                }
                // rebuild neighbor rescale from updated scales (intra-warp)
                const int iMp = __shfl_up_sync(0xffffffffu, iM, 1);
                int k = iMp - iM;
                k = (k > 125) ? 125 : ((k < -127) ? -127 : k);
                fp = __int_as_float((unsigned)(k + 127) << 23);
                if (lane == 0) fp = 0.0f;
            }

            const float vp3 = __shfl_up_sync(0xffffffffu, v3, 1);
            const float vp  = vp3 * fp;      // fp==0 masks lane 0
            const float nv0 = (v0 + vp) * g0[j];
            const float nv1 = (v1 + v0 + vp * sk1) * g1[j];
            const float nv2 = (v2 + v1) * g0[j];
            const float nv3 = (v3 + v2 + v1 * sk3) * g3[j];
            v0 = nv0; v1 = nv1; v2 = nv2; v3 = nv3;

            if (isLast) {
                const int t = (win << 4) + j;
                if (t == len - 1 && own) {       // record final states
                    if (sb == end)         { FinV[0] = v0; FinI[0] = iM; }
                    if (sb + 2 == end)     { FinV[0] = v2; FinI[0] = iM; }
                    if (sb + 1 == end - 1) { FinV[1] = v1; FinI[1] = iM; }
                    if (sb + 3 == end - 1) { FinV[1] = v3; FinI[1] = iM; }
                }
            }
        }

        // ---- window boundary ----
        // 1) per-thread renorm: pull exponent of max(v0..v3) into iM.
        const float mx = fmaxf(fmaxf(v0, v1), fmaxf(v2, v3));
        if (mx > 0.0f) {
            const int e = (int)(__float_as_uint(mx) >> 23) - 127;
            iM += e;
            const float sc = __int_as_float((unsigned)(127 - e) << 23);
            v0 *= sc; v1 *= sc; v2 *= sc; v3 *= sc;
        }
        // 2) owners publish; barrier; reload record + adoption scale in parallel.
        const int ab = win & 1;
        if (own) {
            As[ab][pidx] = make_float4(v0, v1, v2, v3);
            Ai[ab][pidx] = iM;
        }
        __syncthreads();
        const float4 pv  = As[ab][pidx];
        const int    iMr = Ai[ab][pidx];
        const int    iMa = Ai[ab][(pidx >= 8) ? (pidx - 8) : 0];  // parallel load
        v0 = pv.x; v1 = pv.y; v2 = pv.z; v3 = pv.w;
        // 3) unreached threads adopt the propagated scale (select, no extra hop).
        iM = (fmaxf(fmaxf(v0, v1), fmaxf(v2, v3)) == 0.0f) ? iMa : iMr;

        // 4) fixed per-window neighbor rescale from post-adoption scales.
        const int iMp = __shfl_up_sync(0xffffffffu, iM, 1);
        int k = iMp - iM;
        k = (k > 125) ? 125 : ((k < -127) ? -127 : k);
        fp = __int_as_float((unsigned)(k + 127) << 23);  // k=-127 -> exact 0
        if (lane == 0) fp = 0.0f;
    }

    __syncthreads();
    if (tid == 0) {
        const float f0 = __log2f(FinV[0]) + (float)FinI[0];
        const float f1 = __log2f(FinV[1]) + (float)FinI[1];
        const float mm   = fmaxf(f0, f1);
        const float fin2 = mm + __log2f(exp2f(f0 - mm) + exp2f(f1 - mm));
        const float ctc  = -(fin2 * LN2);
        const float fw   = 1.0f - __expf(-ctc);     // focal: alpha=1, gamma=2
        const double contrib = (double)(ctc * (fw * fw));

        // Deterministic reduction: integer fixed-point atomic (exactly
        // associative), last CTA converts + writes + resets for next replay.
        const unsigned long long q =
            (unsigned long long)(long long)(contrib * FIXSCALE + 0.5);
        atomicAdd(&g_acc, q);
        __threadfence();
        const unsigned rank = atomicAdd(&g_done, 1u);
        if (rank == N_DIM - 1) {
            const unsigned long long total = atomicAdd(&g_acc, 0ull);
            out[0] = (float)((double)total / FIXSCALE);
            g_acc  = 0ull;          // reset for the next graph replay
            g_done = 0u;
        }
    }
}

extern "C" void kernel_launch(void* const* d_in, const int* in_sizes, int n_in,
                              void* d_out, int out_size)
{
    const float* predicts      = (const float*)d_in[0];
    const int*   labels        = (const int*)  d_in[1];
    // d_in[2] = ref_labels (unused), d_in[5] = ref_length (unused)
    const int*   preds_lengths = (const int*)  d_in[3];
    const int*   label_lengths = (const int*)  d_in[4];
    float*       out           = (float*)d_out;

    ctc_forward_kernel<<<N_DIM, NTHR>>>(predicts, labels, preds_lengths,
                                        label_lengths, out);
}

// round 14
// speedup vs baseline: 1.2949x; 1.2225x over previous
#include <cuda_runtime.h>
#include <cuda_bf16.h>

// Problem dims (fixed by setup_inputs)
#define T_DIM 2048
#define N_DIM 128
#define C_DIM 96
#define NC    (N_DIM * C_DIM)
#define L_DIM 200
#define S_EXT 401            // 2*L+1
#define NWARP 4
#define NTHR  (NWARP * 32)   // 128
#define KWIN  8              // ticks per window (= barrier period)
#define SPT   4              // states per thread
#define OWNS  112            // owned slots per warp (28 threads * 4)
#define HALO  16             // left halo slots per warp (= 2*KWIN = 4 threads)
#define NREC  ((NWARP * OWNS + HALO) / SPT)   // 116 records
#define LN2   0.69314718055994530942f
#define FIXSCALE 1024.0      // fixed-point scale for deterministic reduction

// Deterministic cross-CTA reduction state (reset by the last CTA each call).
__device__ unsigned long long g_acc  = 0ull;
__device__ unsigned int       g_done = 0u;

// One CTA per batch element. CTC forward, per-thread block-floating-point
// (4 adjacent states per thread, linear floats + power-of-two scale iM).
// R13 = R10 shape + RE-ASSOCIATED recurrence: per-window coefficient arrays
// c1 = (fp*sk1)*P1 and c3 = sk3*P3 turn each carried-chain hop into a single
// FFMA, cutting the lockstep cycle shfl->nv1->nv3->shfl from ~54 to ~34 cy
// per 2 ticks. P gathers + SMEM commit stay at window top (off-chain);
// depth-3 LDG staging pipeline; in-kernel deterministic reduction.
__global__ __launch_bounds__(NTHR, 1)
void ctc_forward_kernel(const float* __restrict__ predicts,   // (T, N, C)
                        const int*   __restrict__ labels,     // (N, L)
                        const int*   __restrict__ preds_lengths,
                        const int*   __restrict__ label_lengths,
                        float*       __restrict__ out)
{
    const int tid  = threadIdx.x;
    const int n    = blockIdx.x;
    const int w    = tid >> 5;
    const int lane = tid & 31;
    const int sb   = OWNS * w - HALO + SPT * lane;   // first (even) slot
    const bool own = (lane >= HALO / SPT);           // lanes 0..3 are halo
    const int pidx = (sb + HALO) >> 2;               // 28*w + lane

    __shared__ float4 As[2][NREC];    // ping-pong (v0,v1,v2,v3)
    __shared__ int    Ai[2][NREC];    // ping-pong iM
    __shared__ float  Pb[2 * KWIN * C_DIM];  // linear probs, double-buffered
    __shared__ float  FinV[2];
    __shared__ int    FinI[2];

    if (tid < HALO / SPT) {           // permanent zero-pads for slots < 0
        As[0][tid] = make_float4(0.f, 0.f, 0.f, 0.f);
        As[1][tid] = make_float4(0.f, 0.f, 0.f, 0.f);
        Ai[0][tid] = 0; Ai[1][tid] = 0;
    }

    // Odd slots sb+1, sb+3 carry labels; even slots are blanks (no skip).
    int ext1 = 0, ext3 = 0;
    float sk1 = 0.0f, sk3 = 0.0f;
    {
        const int s1 = sb + 1, s3 = sb + 3;
        if (s1 >= 1 && s1 < S_EXT) {
            const int k = s1 >> 1;
            ext1 = labels[n * L_DIM + k];
            if (s1 >= 3) sk1 = (ext1 != labels[n * L_DIM + k - 1]) ? 1.0f : 0.0f;
        }
        if (s3 >= 1 && s3 < S_EXT) {
            const int k = s3 >> 1;
            ext3 = labels[n * L_DIM + k];
            if (s3 >= 3) sk3 = (ext3 != labels[n * L_DIM + k - 1]) ? 1.0f : 0.0f;
        }
    }
    const int len     = preds_lengths[n];
    const int end     = 2 * label_lengths[n];
    const int lastwin = (len - 1) >> 3;

    // Cooperative staging geometry: 8 rows x 96 classes = 768 floats, 6/thread.
    const float* gbase = predicts + (size_t)n * C_DIM;
    int off_q[6], r_q[6];
#pragma unroll
    for (int q = 0; q < 6; ++q) {
        const int idx = tid + q * NTHR;
        const int r = idx / C_DIM, c = idx - r * C_DIM;
        r_q[q]   = r;
        off_q[q] = r * NC + c;
    }

    // Pre-stage rows [0,8) into buffer 0; prime the depth-3 register pipeline
    // with LDGs for windows 1..3 (rows 8..31; len >= 1024 so always valid).
    float stgA[6], stgB[6], stgC[6];
#pragma unroll
    for (int q = 0; q < 6; ++q) {
        Pb[tid + q * NTHR] = __expf(__ldg(gbase + off_q[q]));
        stgA[q] = __ldg(gbase + off_q[q] + (size_t)(1 * KWIN) * NC);
        stgB[q] = __ldg(gbase + off_q[q] + (size_t)(2 * KWIN) * NC);
        stgC[q] = __ldg(gbase + off_q[q] + (size_t)(3 * KWIN) * NC);
    }
    __syncthreads();

    float v0 = (sb == 0) ? 1.0f : 0.0f;   // virtual alpha_{-1}: 1 at slot 0
    float v1 = 0.f, v2 = 0.f, v3 = 0.f;
    int   iM = 0;
    float fp = (lane == 0) ? 0.0f : 1.0f; // all scales equal at t=0
    const int nwin = (len + KWIN - 1) >> 3;   // len uniform per CTA

    for (int win = 0; win < nwin; ++win) {
        // --- window top: gather P values + build chain coefficients ---
        const float* prow = Pb + ((win & 1) ? KWIN * C_DIM : 0);
        const float u1 = fp * sk1;        // scalar per window
        float g0[KWIN], g1[KWIN], g3[KWIN], c1[KWIN], c3[KWIN];
#pragma unroll
        for (int j = 0; j < KWIN; ++j) {
            const float* r = prow + j * C_DIM;
            g0[j] = r[0];                 // blank (broadcast, conflict-free)
            g1[j] = r[ext1];
            g3[j] = r[ext3];
            c1[j] = u1 * g1[j];           // chain coeff: vp -> nv1 in one FFMA
            c3[j] = sk3 * g3[j];          // chain coeff: v1 -> nv3 in one FFMA
        }

        // --- commit next window's rows into the OTHER buffer, then refill
        //     the staging set with rows 4 windows ahead ---
        {
            float* dst = Pb + ((win & 1) ? 0 : KWIN * C_DIM);
            const int tnext = (win + 4) * KWIN;
            const int set   = win % 3;
            if (set == 0) {
#pragma unroll
                for (int q = 0; q < 6; ++q) {
                    dst[tid + q * NTHR] = __expf(stgA[q]);
                    stgA[q] = (tnext + r_q[q] < T_DIM)
                              ? __ldg(gbase + off_q[q] + (size_t)tnext * NC) : 0.0f;
                }
            } else if (set == 1) {
#pragma unroll
                for (int q = 0; q < 6; ++q) {
                    dst[tid + q * NTHR] = __expf(stgB[q]);
                    stgB[q] = (tnext + r_q[q] < T_DIM)
                              ? __ldg(gbase + off_q[q] + (size_t)tnext * NC) : 0.0f;
                }
            } else {
#pragma unroll
                for (int q = 0; q < 6; ++q) {
                    dst[tid + q * NTHR] = __expf(stgC[q]);
                    stgC[q] = (tnext + r_q[q] < T_DIM)
                              ? __ldg(gbase + off_q[q] + (size_t)tnext * NC) : 0.0f;
                }
            }
        }

        // --- tick loop: 1 shfl + FMA dataflow; chain hops are single FFMAs ---
        if (win != lastwin) {
#pragma unroll
            for (int j = 0; j < KWIN; ++j) {
                const float vp  = __shfl_up_sync(0xffffffffu, v3, 1);
                const float nv0 = __fmaf_rn(vp, fp, v0) * g0[j];
                const float nv1 = __fmaf_rn(vp, c1[j], (v1 + v0) * g1[j]);
                const float nv2 = (v2 + v1) * g0[j];
                const float nv3 = __fmaf_rn(v1, c3[j], (v3 + v2) * g3[j]);
                v0 = nv0; v1 = nv1; v2 = nv2; v3 = nv3;
            }
        } else {
#pragma unroll
            for (int j = 0; j < KWIN; ++j) {
                const int t = (win << 3) + j;
                const float vp  = __shfl_up_sync(0xffffffffu, v3, 1);
                const float nv0 = __fmaf_rn(vp, fp, v0) * g0[j];
                const float nv1 = __fmaf_rn(vp, c1[j], (v1 + v0) * g1[j]);
                const float nv2 = (v2 + v1) * g0[j];
                const float nv3 = __fmaf_rn(v1, c3[j], (v3 + v2) * g3[j]);
                v0 = nv0; v1 = nv1; v2 = nv2; v3 = nv3;

                if (t == len - 1 && own) {       // record final states
                    if (sb == end)         { FinV[0] = v0; FinI[0] = iM; }
                    if (sb + 2 == end)     { FinV[0] = v2; FinI[0] = iM; }
                    if (sb + 1 == end - 1) { FinV[1] = v1; FinI[1] = iM; }
                    if (sb + 3 == end - 1) { FinV[1] = v3; FinI[1] = iM; }
                }
            }
        }

        // ---- window boundary ----
        // 1) per-thread renorm: pull exponent of max(v0..v3) into iM.
        const float mx = fmaxf(fmaxf(v0, v1), fmaxf(v2, v3));
        if (mx > 0.0f) {
            const int e = (int)(__float_as_uint(mx) >> 23) - 127;
            iM += e;
            const float sc = __int_as_float((unsigned)(127 - e) << 23);
            v0 *= sc; v1 *= sc; v2 *= sc; v3 *= sc;
        }
        // 2) owners publish; barrier; reload record + adoption scale in parallel.
        const int ab = win & 1;
        if (own) {
            As[ab][pidx] = make_float4(v0, v1, v2, v3);
            Ai[ab][pidx] = iM;
        }
        __syncthreads();
        const float4 pv  = As[ab][pidx];
        const int    iMr = Ai[ab][pidx];
        const int    iMa = Ai[ab][(pidx >= 4) ? (pidx - 4) : 0];  // parallel load
        v0 = pv.x; v1 = pv.y; v2 = pv.z; v3 = pv.w;
        // 3) unreached threads adopt the propagated scale (select, no extra hop).
        iM = (fmaxf(fmaxf(v0, v1), fmaxf(v2, v3)) == 0.0f) ? iMa : iMr;

        // 4) fixed per-window neighbor rescale from post-adoption scales.
        const int iMp = __shfl_up_sync(0xffffffffu, iM, 1);
        int k = iMp - iM;
        k = (k > 125) ? 125 : ((k < -127) ? -127 : k);
        fp = __int_as_float((unsigned)(k + 127) << 23);  // k=-127 -> exact 0
        if (lane == 0) fp = 0.0f;
    }

    __syncthreads();
    if (tid == 0) {
        const float f0 = __log2f(FinV[0]) + (float)FinI[0];
        const float f1 = __log2f(FinV[1]) + (float)FinI[1];
        const float mm   = fmaxf(f0, f1);
        const float fin2 = mm + __log2f(exp2f(f0 - mm) + exp2f(f1 - mm));
        const float ctc  = -(fin2 * LN2);
        const float fw   = 1.0f - __expf(-ctc);     // focal: alpha=1, gamma=2
        const double contrib = (double)(ctc * (fw * fw));

        // Deterministic reduction: integer fixed-point atomic (exactly
        // associative), last CTA converts + writes + resets for next replay.
        const unsigned long long q =
            (unsigned long long)(long long)(contrib * FIXSCALE + 0.5);
        atomicAdd(&g_acc, q);
        __threadfence();
        const unsigned rank = atomicAdd(&g_done, 1u);
        if (rank == N_DIM - 1) {
            const unsigned long long total = atomicAdd(&g_acc, 0ull);
            out[0] = (float)((double)total / FIXSCALE);
            g_acc  = 0ull;          // reset for the next graph replay
            g_done = 0u;
        }
    }
}

extern "C" void kernel_launch(void* const* d_in, const int* in_sizes, int n_in,
                              void* d_out, int out_size)
{
    const float* predicts      = (const float*)d_in[0];
    const int*   labels        = (const int*)  d_in[1];
    // d_in[2] = ref_labels (unused), d_in[5] = ref_length (unused)
    const int*   preds_lengths = (const int*)  d_in[3];
    const int*   label_lengths = (const int*)  d_in[4];
    float*       out           = (float*)d_out;

    ctc_forward_kernel<<<N_DIM, NTHR>>>(predicts, labels, preds_lengths,
                                        label_lengths, out);
}